// round 3
// baseline (speedup 1.0000x reference)
#include <cuda_runtime.h>
#include <cstdint>

#define BB  4
#define QQ  512
#define MM  512
#define PPQ 128
#define HID 1024
#define HH  16
#define SS  64
#define RR  1024
#define RP  1536

// -------- scratch (device globals; no allocations allowed) --------
__device__ float g_ctx[BB*RR*HID];   // concat(mems, content)   [4,1024,1024]
__device__ float g_kc [BB*RR*HID];   // key_content             [4,1024,16,64]
__device__ float g_v  [BB*RR*HID];   // value
__device__ float g_kp [BB*RP*HID];   // key_position            [4,1536,16,64]
__device__ float g_qc [BB*QQ*HID];   // content query proj      [4,512,16,64]
__device__ float g_qq [BB*PPQ*HID];  // query-stream proj       [4,128,16,64]
__device__ float g_ac [BB*QQ*HID];   // content attn out
__device__ float g_aq [BB*PPQ*HID];  // query attn out
__device__ int   g_tpos[BB*PPQ];

// -------- build contexts = concat(mems, content_inputs) --------
__global__ void build_ctx(const float* __restrict__ mems, const float* __restrict__ content)
{
    int idx = blockIdx.x * blockDim.x + threadIdx.x;       // float4 index
    const int total = BB*RR*HID/4;
    if (idx >= total) return;
    int d4  = idx & (HID/4 - 1);
    int row = idx / (HID/4);
    int n = row >> 10, r = row & 1023;
    const float* src = (r < MM) ? (mems    + ((size_t)n*MM + r)       * HID)
                                : (content + ((size_t)n*QQ + (r-MM))  * HID);
    ((float4*)g_ctx)[idx] = ((const float4*)src)[d4];
}

// -------- tpos[n,p] = argmax_q target_mapping[n,p,q] (one-hot) --------
__global__ void find_tpos(const float* __restrict__ tm)
{
    int i = threadIdx.x;                                   // 512 = B*P
    const float* row = tm + (size_t)i * QQ;
    int q = 0;
    for (int j = 0; j < QQ; j++) if (row[j] > 0.5f) q = j;
    g_tpos[i] = q;
}

// -------- tiled fp32 SGEMM: C[m,1024] = A[m,1024] @ B[1024,1024] --------
// block tile 128x64, K-tile 16, 256 threads, 8x4 microtile
__global__ void sgemm128x64(const float* __restrict__ A, const float* __restrict__ B,
                            float* __restrict__ C)
{
    __shared__ float As[16][132];
    __shared__ float Bs[16][68];
    const int m0 = blockIdx.y * 128;
    const int n0 = blockIdx.x * 64;
    const int tid = threadIdx.x;
    const int tx = tid & 15, ty = tid >> 4;
    float acc[8][4];
#pragma unroll
    for (int i = 0; i < 8; i++)
#pragma unroll
        for (int j = 0; j < 4; j++) acc[i][j] = 0.f;

    for (int kt = 0; kt < 1024; kt += 16) {
#pragma unroll
        for (int u = 0; u < 2; u++) {
            int f = tid + u*256;
            int row = f >> 2, k4 = f & 3;
            float4 v = *(const float4*)(A + (size_t)(m0+row)*1024 + kt + k4*4);
            As[k4*4+0][row] = v.x; As[k4*4+1][row] = v.y;
            As[k4*4+2][row] = v.z; As[k4*4+3][row] = v.w;
        }
        {
            int k = tid >> 4, n4 = tid & 15;
            *(float4*)&Bs[k][n4*4] = *(const float4*)(B + (size_t)(kt+k)*1024 + n0 + n4*4);
        }
        __syncthreads();
#pragma unroll
        for (int k = 0; k < 16; k++) {
            float a[8], b[4];
            *(float4*)(a)   = *(float4*)&As[k][ty*8];
            *(float4*)(a+4) = *(float4*)&As[k][ty*8+4];
            *(float4*)(b)   = *(float4*)&Bs[k][tx*4];
#pragma unroll
            for (int i = 0; i < 8; i++)
#pragma unroll
                for (int j = 0; j < 4; j++) acc[i][j] += a[i]*b[j];
        }
        __syncthreads();
    }
#pragma unroll
    for (int i = 0; i < 8; i++) {
        float4 v = make_float4(acc[i][0], acc[i][1], acc[i][2], acc[i][3]);
        *(float4*)(C + (size_t)(m0+ty*8+i)*1024 + n0 + tx*4) = v;
    }
}

// -------- fused attention: content + rel-shifted position + segment + softmax + AV --------
// grid: (NQ/16, H, B); 256 threads; dynamic smem:
//   logits[16*1024] | kt[128*65] | qcs[16*64] | qps[16*64] | seg0[16] seg1[16] qrow[16]
#define ATTN_SMEM_FLOATS (16*1024 + 128*65 + 16*64 + 16*64 + 48)
#define ATTN_SMEM_BYTES  (ATTN_SMEM_FLOATS*4)

__global__ void attn_kernel(const float* __restrict__ Qp, int NQ,
                            const float* __restrict__ KC, const float* __restrict__ V,
                            const float* __restrict__ KP,
                            const float* __restrict__ segenc,
                            const int* __restrict__ segmat,
                            const float* __restrict__ mask,
                            const float* __restrict__ cb, const float* __restrict__ pb,
                            const float* __restrict__ sb,
                            const int* __restrict__ tpos,
                            float* __restrict__ Out)
{
    extern __shared__ float sm[];
    float* logits = sm;                      // 16 x 1024
    float* kt     = sm + 16*1024;            // 128 x 65 (pitch 65 => conflict-free column reads)
    float* qcs    = kt + 128*65;             // 16 x 64  (q + content_bias)
    float* qps    = qcs + 16*64;             // 16 x 64  (q + position_bias)
    float* seg0   = qps + 16*64;             // 16
    float* seg1   = seg0 + 16;               // 16
    int*   qrow   = (int*)(seg1 + 16);       // 16

    const int n  = blockIdx.z, h = blockIdx.y;
    const int q0 = blockIdx.x * 16;
    const int tid = threadIdx.x;

    for (int u = tid; u < 16*64; u += 256) {
        int l = u >> 6, s = u & 63;
        float qv = Qp[(((size_t)n*NQ + q0 + l)*HH + h)*SS + s];
        qcs[u] = qv + cb[h*SS + s];
        qps[u] = qv + pb[h*SS + s];
    }
    if (tid < 16) qrow[tid] = tpos ? tpos[n*PPQ + q0 + tid] : (q0 + tid);
    if (tid < 32) {
        int l = tid >> 1, g = tid & 1;
        float acc = 0.f;
        const float* qr = Qp + (((size_t)n*NQ + q0 + l)*HH + h)*SS;
        const float* se = segenc + ((size_t)g*HH + h)*SS;
        for (int s = 0; s < SS; s++) acc += (qr[s] + sb[h*SS + s]) * se[s];
        if (g) seg1[l] = acc; else seg0[l] = acc;
    }
    __syncthreads();

    const int qg = tid >> 5;   // 0..7  -> q pair
    const int rg = tid & 31;   // 0..31 -> r lane (strided x4)

    // ---- Phase A1: content logits = (q+cb) . KC ----
    for (int rt = 0; rt < 8; rt++) {
        for (int u = tid; u < 128*16; u += 256) {
            int rl = u >> 4, s4 = u & 15;
            float4 v = *(const float4*)(KC + ((((size_t)n*RR + rt*128 + rl)*HH + h) << 6) + s4*4);
            float* d = kt + rl*65 + s4*4;
            d[0]=v.x; d[1]=v.y; d[2]=v.z; d[3]=v.w;
        }
        __syncthreads();
        float a00=0,a01=0,a02=0,a03=0,a10=0,a11=0,a12=0,a13=0;
        const float* qa_p = qcs + (qg*2)*64;
        const float* qb_p = qa_p + 64;
#pragma unroll 4
        for (int s = 0; s < 64; s++) {
            float qa = qa_p[s], qb = qb_p[s];
            float k0 = kt[(rg     )*65 + s];
            float k1 = kt[(rg + 32)*65 + s];
            float k2 = kt[(rg + 64)*65 + s];
            float k3 = kt[(rg + 96)*65 + s];
            a00 += qa*k0; a01 += qa*k1; a02 += qa*k2; a03 += qa*k3;
            a10 += qb*k0; a11 += qb*k1; a12 += qb*k2; a13 += qb*k3;
        }
        int b0 = (qg*2)*1024 + rt*128 + rg;
        int b1 = b0 + 1024;
        logits[b0]=a00; logits[b0+32]=a01; logits[b0+64]=a02; logits[b0+96]=a03;
        logits[b1]=a10; logits[b1+32]=a11; logits[b1+64]=a12; logits[b1+96]=a13;
        __syncthreads();
    }

    // ---- Phase A2: position logits, rel_shift scatter: logit(q,r) += PA[q, r+512-q] ----
    for (int pt = 0; pt < 12; pt++) {
        for (int u = tid; u < 128*16; u += 256) {
            int rl = u >> 4, s4 = u & 15;
            float4 v = *(const float4*)(KP + ((((size_t)n*RP + pt*128 + rl)*HH + h) << 6) + s4*4);
            float* d = kt + rl*65 + s4*4;
            d[0]=v.x; d[1]=v.y; d[2]=v.z; d[3]=v.w;
        }
        __syncthreads();
        float a0[4] = {0,0,0,0}, a1[4] = {0,0,0,0};
        const float* qa_p = qps + (qg*2)*64;
        const float* qb_p = qa_p + 64;
#pragma unroll 4
        for (int s = 0; s < 64; s++) {
            float qa = qa_p[s], qb = qb_p[s];
#pragma unroll
            for (int j = 0; j < 4; j++) {
                float kv = kt[(rg + 32*j)*65 + s];
                a0[j] += qa*kv; a1[j] += qb*kv;
            }
        }
        int l0 = qg*2, l1 = l0 + 1;
        int qp0 = qrow[l0], qp1 = qrow[l1];
#pragma unroll
        for (int j = 0; j < 4; j++) {
            int pp = pt*128 + rg + 32*j;
            int r0 = pp - 512 + qp0;
            int r1 = pp - 512 + qp1;
            if (r0 >= 0 && r0 < RR) logits[l0*1024 + r0] += a0[j];
            if (r1 >= 0 && r1 < RR) logits[l1*1024 + r1] += a1[j];
        }
        __syncthreads();
    }

    // ---- Phase A3: segment select + mask + scale + softmax (in smem) ----
    {
        int lq = tid >> 4, lane = tid & 15;
        int qq = qrow[lq];
        const float* mrow = mask + ((size_t)n*QQ + qq)*RR;
        const int* srow = segmat + ((size_t)n*QQ + qq)*RR;
        float s1v = seg1[lq], s0v = seg0[lq];
        float* lrow = logits + lq*1024;
        float mx = -3.4e38f;
        for (int i = 0; i < 64; i++) {
            int c = lane + 16*i;
            float lg = lrow[c] + (srow[c] ? s1v : s0v);
            lg = lg * 0.125f + mrow[c] * (-1e9f);
            lrow[c] = lg;
            mx = fmaxf(mx, lg);
        }
        for (int o = 8; o; o >>= 1) mx = fmaxf(mx, __shfl_xor_sync(0xffffffffu, mx, o, 16));
        float sum = 0.f;
        for (int i = 0; i < 64; i++) {
            int c = lane + 16*i;
            float e = __expf(lrow[c] - mx);
            lrow[c] = e;
            sum += e;
        }
        for (int o = 8; o; o >>= 1) sum += __shfl_xor_sync(0xffffffffu, sum, o, 16);
        float inv = __fdividef(1.f, sum);
        for (int i = 0; i < 64; i++) lrow[lane + 16*i] *= inv;
    }
    __syncthreads();

    // ---- Phase B: out = weights @ V ----
    {
        const int sg = rg;
        float b00=0, b01=0, b10=0, b11=0;
        const float* l0row = logits + (qg*2)*1024;
        const float* l1row = l0row + 1024;
        for (int rt = 0; rt < 8; rt++) {
            for (int u = tid; u < 128*16; u += 256) {
                int rl = u >> 4, s4 = u & 15;
                float4 v = *(const float4*)(V + ((((size_t)n*RR + rt*128 + rl)*HH + h) << 6) + s4*4);
                float* d = kt + rl*65 + s4*4;
                d[0]=v.x; d[1]=v.y; d[2]=v.z; d[3]=v.w;
            }
            __syncthreads();
#pragma unroll 4
            for (int rr = 0; rr < 128; rr++) {
                float w0 = l0row[rt*128 + rr];
                float w1 = l1row[rt*128 + rr];
                float v0 = kt[rr*65 + sg];
                float v1 = kt[rr*65 + sg + 32];
                b00 += w0*v0; b01 += w0*v1; b10 += w1*v0; b11 += w1*v1;
            }
            __syncthreads();
        }
        size_t ob = (((size_t)n*NQ + q0 + qg*2)*HH + h)*SS;
        Out[ob + sg]            = b00;
        Out[ob + sg + 32]       = b01;
        Out[ob + 1024 + sg]     = b10;
        Out[ob + 1024 + sg + 32] = b11;
    }
}

// -------------------- launch --------------------
extern "C" void kernel_launch(void* const* d_in, const int* in_sizes, int n_in,
                              void* d_out, int out_size)
{
    const float* content = (const float*)d_in[0];
    const float* query   = (const float*)d_in[1];
    const float* posenc  = (const float*)d_in[2];
    const float* segenc  = (const float*)d_in[3];
    const int*   segmat  = (const int*)d_in[4];
    const float* tmap    = (const float*)d_in[5];
    const float* cmask   = (const float*)d_in[6];
    const float* qmask   = (const float*)d_in[7];
    const float* cb      = (const float*)d_in[8];
    const float* pb      = (const float*)d_in[9];
    const float* sb      = (const float*)d_in[10];
    const float* mems    = (const float*)d_in[11];
    const float* Wq      = (const float*)d_in[12];
    const float* Wkc     = (const float*)d_in[13];
    const float* Wv      = (const float*)d_in[14];
    const float* Wkp     = (const float*)d_in[15];
    const float* Wo      = (const float*)d_in[16];
    float* out = (float*)d_out;

    float *p_ctx, *p_kc, *p_v, *p_kp, *p_qc, *p_qq, *p_ac, *p_aq;
    int* p_tpos;
    cudaGetSymbolAddress((void**)&p_ctx, g_ctx);
    cudaGetSymbolAddress((void**)&p_kc,  g_kc);
    cudaGetSymbolAddress((void**)&p_v,   g_v);
    cudaGetSymbolAddress((void**)&p_kp,  g_kp);
    cudaGetSymbolAddress((void**)&p_qc,  g_qc);
    cudaGetSymbolAddress((void**)&p_qq,  g_qq);
    cudaGetSymbolAddress((void**)&p_ac,  g_ac);
    cudaGetSymbolAddress((void**)&p_aq,  g_aq);
    cudaGetSymbolAddress((void**)&p_tpos, g_tpos);

    cudaFuncSetAttribute(attn_kernel, cudaFuncAttributeMaxDynamicSharedMemorySize, ATTN_SMEM_BYTES);

    build_ctx<<<(BB*RR*HID/4 + 255)/256, 256>>>(mems, content);
    find_tpos<<<1, 512>>>(tmap);

    dim3 gKCV(16, 32);  // 4096 rows
    sgemm128x64<<<gKCV, 256>>>(p_ctx, Wkc, p_kc);
    sgemm128x64<<<gKCV, 256>>>(p_ctx, Wv,  p_v);
    dim3 gKP(16, 48);   // 6144 rows
    sgemm128x64<<<gKP, 256>>>(posenc, Wkp, p_kp);
    dim3 gQC(16, 16);   // 2048 rows
    sgemm128x64<<<gQC, 256>>>(content, Wq, p_qc);
    dim3 gQQ(16, 4);    // 512 rows
    sgemm128x64<<<gQQ, 256>>>(query, Wq, p_qq);

    dim3 gac(QQ/16, HH, BB);
    attn_kernel<<<gac, 256, ATTN_SMEM_BYTES>>>(p_qc, QQ, p_kc, p_v, p_kp, segenc, segmat,
                                               cmask, cb, pb, sb, nullptr, p_ac);
    dim3 gaq(PPQ/16, HH, BB);
    attn_kernel<<<gaq, 256, ATTN_SMEM_BYTES>>>(p_qq, PPQ, p_kc, p_v, p_kp, segenc, segmat,
                                               qmask, cb, pb, sb, p_tpos, p_aq);

    sgemm128x64<<<gQC, 256>>>(p_ac, Wo, out);
    sgemm128x64<<<gQQ, 256>>>(p_aq, Wo, out + (size_t)BB*QQ*HID);
}

// round 5
// speedup vs baseline: 1.4145x; 1.4145x over previous
#include <cuda_runtime.h>
#include <cstdint>

#define BB  4
#define QQ  512
#define MM  512
#define PPQ 128
#define HID 1024
#define HH  16
#define SS  64
#define RR  1024
#define RP  1536

// -------- scratch (device globals; no allocations allowed) --------
__device__ float g_ctx[BB*RR*HID];   // concat(mems, content)
__device__ float g_kc [BB*RR*HID];
__device__ float g_v  [BB*RR*HID];
__device__ float g_kp [BB*RP*HID];
__device__ float g_qc [BB*QQ*HID];
__device__ float g_qq [BB*PPQ*HID];
__device__ float g_ac [BB*QQ*HID];
__device__ float g_aq [BB*PPQ*HID];
__device__ int   g_tpos[BB*PPQ];

// ================= helpers =================
__device__ __forceinline__ uint32_t smem_u32(const void* p){
    uint32_t a;
    asm("{ .reg .u64 t; cvta.to.shared.u64 t, %1; cvt.u32.u64 %0, t; }" : "=r"(a) : "l"(p));
    return a;
}
__device__ __forceinline__ void cpasync16(uint32_t s, const void* g){
    asm volatile("cp.async.cg.shared.global [%0], [%1], 16;" :: "r"(s), "l"(g));
}
__device__ __forceinline__ void cpasync_commit(){ asm volatile("cp.async.commit_group;" ::: "memory"); }
__device__ __forceinline__ void cpasync_wait0(){ asm volatile("cp.async.wait_group 0;" ::: "memory"); }
__device__ __forceinline__ uint32_t f2tf32(float x){
    uint32_t r;
    asm("cvt.rna.tf32.f32 %0, %1;" : "=r"(r) : "f"(x));
    return r;
}
__device__ __forceinline__ void mma_tf32(float* c, const uint32_t* a, const uint32_t* b){
    asm volatile("mma.sync.aligned.m16n8k8.row.col.f32.tf32.tf32.f32 "
        "{%0,%1,%2,%3}, {%4,%5,%6,%7}, {%8,%9}, {%0,%1,%2,%3};"
        : "+f"(c[0]),"+f"(c[1]),"+f"(c[2]),"+f"(c[3])
        : "r"(a[0]),"r"(a[1]),"r"(a[2]),"r"(a[3]), "r"(b[0]),"r"(b[1]));
}

// ================= misc kernels =================
__global__ void build_ctx(const float* __restrict__ mems, const float* __restrict__ content)
{
    int idx = blockIdx.x * blockDim.x + threadIdx.x;
    const int total = BB*RR*HID/4;
    if (idx >= total) return;
    int d4  = idx & (HID/4 - 1);
    int row = idx / (HID/4);
    int n = row >> 10, r = row & 1023;
    const float* src = (r < MM) ? (mems + ((size_t)n*MM + r)*HID)
                                : (content + ((size_t)n*QQ + (r-MM))*HID);
    ((float4*)g_ctx)[idx] = ((const float4*)src)[d4];
}

__global__ void find_tpos(const float* __restrict__ tm)
{
    int i = threadIdx.x;
    const float* row = tm + (size_t)i * QQ;
    int q = 0;
    for (int j = 0; j < QQ; j++) if (row[j] > 0.5f) q = j;
    g_tpos[i] = q;
}

// ================= tf32 mma GEMM =================
// C[m,1024] = A[m,1024] @ W[1024,1024]  (W row-major [k][n], exactly as given)
// block tile 128x128, 8 warps (4M x 2N), warp tile 32x64, K-tile 16, double buffered
__global__ __launch_bounds__(256, 2) void gemm_mma(const float* __restrict__ A,
                                                   const float* __restrict__ W,
                                                   float* __restrict__ C)
{
    __shared__ float As[2][128][20];   // [buf][m][k]  pad 20 -> conflict-free frags
    __shared__ float Bs[2][16][136];   // [buf][k][n]  pad 136 -> conflict-free frags

    const int tid  = threadIdx.x;
    const int wid  = tid >> 5, lane = tid & 31;
    const int wm   = wid & 3,  wn   = wid >> 2;     // warp coords: 4 in M, 2 in N
    const int g    = lane >> 2, t   = lane & 3;     // fragment coords
    const int m0   = blockIdx.y * 128;
    const int n0   = blockIdx.x * 128;

    const uint32_t sA = smem_u32(As);
    const uint32_t sB = smem_u32(Bs);

    float c[2][8][4];
#pragma unroll
    for (int i = 0; i < 2; i++)
#pragma unroll
        for (int j = 0; j < 8; j++)
#pragma unroll
            for (int l = 0; l < 4; l++) c[i][j][l] = 0.f;

    auto load_tile = [&](int kt, int buf){
        // A: 128 rows x 16 k-floats = 512 x 16B
#pragma unroll
        for (int i = 0; i < 2; i++) {
            int idx = tid + i*256;
            int row = idx >> 2, k4 = idx & 3;
            cpasync16(sA + (uint32_t)buf*10240u + row*80u + k4*16u,
                      A + (size_t)(m0 + row)*1024 + kt + k4*4);
        }
        // B: 16 k-rows x 128 n-floats = 512 x 16B
#pragma unroll
        for (int i = 0; i < 2; i++) {
            int idx = tid + i*256;
            int kk = idx >> 5, n4 = idx & 31;
            cpasync16(sB + (uint32_t)buf*8704u + kk*544u + n4*16u,
                      W + (size_t)(kt + kk)*1024 + n0 + n4*4);
        }
        cpasync_commit();
    };

    load_tile(0, 0);
    cpasync_wait0();
    __syncthreads();

    for (int kt = 0; kt < 64; kt++) {
        int buf = kt & 1;
        if (kt + 1 < 64) load_tile((kt + 1)*16, buf ^ 1);

        // compute on current buffer
#pragma unroll
        for (int ks = 0; ks < 16; ks += 8) {
            uint32_t af[2][4], bf[8][2];
#pragma unroll
            for (int mt = 0; mt < 2; mt++) {
                int mr = wm*32 + mt*16 + g;
                af[mt][0] = f2tf32(As[buf][mr    ][ks + t    ]);
                af[mt][1] = f2tf32(As[buf][mr + 8][ks + t    ]);
                af[mt][2] = f2tf32(As[buf][mr    ][ks + t + 4]);
                af[mt][3] = f2tf32(As[buf][mr + 8][ks + t + 4]);
            }
#pragma unroll
            for (int nt = 0; nt < 8; nt++) {
                int nc = wn*64 + nt*8 + g;
                bf[nt][0] = f2tf32(Bs[buf][ks + t    ][nc]);
                bf[nt][1] = f2tf32(Bs[buf][ks + t + 4][nc]);
            }
#pragma unroll
            for (int mt = 0; mt < 2; mt++)
#pragma unroll
                for (int nt = 0; nt < 8; nt++)
                    mma_tf32(c[mt][nt], af[mt], bf[nt]);
        }

        cpasync_wait0();
        __syncthreads();
    }

    // epilogue
#pragma unroll
    for (int mt = 0; mt < 2; mt++) {
        int row = m0 + wm*32 + mt*16 + g;
#pragma unroll
        for (int nt = 0; nt < 8; nt++) {
            int col = n0 + wn*64 + nt*8 + 2*t;
            *(float2*)(C + (size_t)row*1024 + col)       = make_float2(c[mt][nt][0], c[mt][nt][1]);
            *(float2*)(C + (size_t)(row + 8)*1024 + col) = make_float2(c[mt][nt][2], c[mt][nt][3]);
        }
    }
}

// ================= fused attention (unchanged) =================
#define ATTN_SMEM_FLOATS (16*1024 + 128*65 + 16*64 + 16*64 + 48)
#define ATTN_SMEM_BYTES  (ATTN_SMEM_FLOATS*4)

__global__ void attn_kernel(const float* __restrict__ Qp, int NQ,
                            const float* __restrict__ KC, const float* __restrict__ V,
                            const float* __restrict__ KP,
                            const float* __restrict__ segenc,
                            const int* __restrict__ segmat,
                            const float* __restrict__ mask,
                            const float* __restrict__ cb, const float* __restrict__ pb,
                            const float* __restrict__ sb,
                            const int* __restrict__ tpos,
                            float* __restrict__ Out)
{
    extern __shared__ float sm[];
    float* logits = sm;
    float* kt     = sm + 16*1024;
    float* qcs    = kt + 128*65;
    float* qps    = qcs + 16*64;
    float* seg0   = qps + 16*64;
    float* seg1   = seg0 + 16;
    int*   qrow   = (int*)(seg1 + 16);

    const int n  = blockIdx.z, h = blockIdx.y;
    const int q0 = blockIdx.x * 16;
    const int tid = threadIdx.x;

    for (int u = tid; u < 16*64; u += 256) {
        int l = u >> 6, s = u & 63;
        float qv = Qp[(((size_t)n*NQ + q0 + l)*HH + h)*SS + s];
        qcs[u] = qv + cb[h*SS + s];
        qps[u] = qv + pb[h*SS + s];
    }
    if (tid < 16) qrow[tid] = tpos ? tpos[n*PPQ + q0 + tid] : (q0 + tid);
    if (tid < 32) {
        int l = tid >> 1, g = tid & 1;
        float acc = 0.f;
        const float* qr = Qp + (((size_t)n*NQ + q0 + l)*HH + h)*SS;
        const float* se = segenc + ((size_t)g*HH + h)*SS;
        for (int s = 0; s < SS; s++) acc += (qr[s] + sb[h*SS + s]) * se[s];
        if (g) seg1[l] = acc; else seg0[l] = acc;
    }
    __syncthreads();

    const int qg = tid >> 5;
    const int rg = tid & 31;

    for (int rt = 0; rt < 8; rt++) {
        for (int u = tid; u < 128*16; u += 256) {
            int rl = u >> 4, s4 = u & 15;
            float4 v = *(const float4*)(KC + ((((size_t)n*RR + rt*128 + rl)*HH + h) << 6) + s4*4);
            float* d = kt + rl*65 + s4*4;
            d[0]=v.x; d[1]=v.y; d[2]=v.z; d[3]=v.w;
        }
        __syncthreads();
        float a00=0,a01=0,a02=0,a03=0,a10=0,a11=0,a12=0,a13=0;
        const float* qa_p = qcs + (qg*2)*64;
        const float* qb_p = qa_p + 64;
#pragma unroll 4
        for (int s = 0; s < 64; s++) {
            float qa = qa_p[s], qb = qb_p[s];
            float k0 = kt[(rg     )*65 + s];
            float k1 = kt[(rg + 32)*65 + s];
            float k2 = kt[(rg + 64)*65 + s];
            float k3 = kt[(rg + 96)*65 + s];
            a00 += qa*k0; a01 += qa*k1; a02 += qa*k2; a03 += qa*k3;
            a10 += qb*k0; a11 += qb*k1; a12 += qb*k2; a13 += qb*k3;
        }
        int b0 = (qg*2)*1024 + rt*128 + rg;
        int b1 = b0 + 1024;
        logits[b0]=a00; logits[b0+32]=a01; logits[b0+64]=a02; logits[b0+96]=a03;
        logits[b1]=a10; logits[b1+32]=a11; logits[b1+64]=a12; logits[b1+96]=a13;
        __syncthreads();
    }

    for (int pt = 0; pt < 12; pt++) {
        for (int u = tid; u < 128*16; u += 256) {
            int rl = u >> 4, s4 = u & 15;
            float4 v = *(const float4*)(KP + ((((size_t)n*RP + pt*128 + rl)*HH + h) << 6) + s4*4);
            float* d = kt + rl*65 + s4*4;
            d[0]=v.x; d[1]=v.y; d[2]=v.z; d[3]=v.w;
        }
        __syncthreads();
        float a0[4] = {0,0,0,0}, a1[4] = {0,0,0,0};
        const float* qa_p = qps + (qg*2)*64;
        const float* qb_p = qa_p + 64;
#pragma unroll 4
        for (int s = 0; s < 64; s++) {
            float qa = qa_p[s], qb = qb_p[s];
#pragma unroll
            for (int j = 0; j < 4; j++) {
                float kv = kt[(rg + 32*j)*65 + s];
                a0[j] += qa*kv; a1[j] += qb*kv;
            }
        }
        int l0 = qg*2, l1 = l0 + 1;
        int qp0 = qrow[l0], qp1 = qrow[l1];
#pragma unroll
        for (int j = 0; j < 4; j++) {
            int pp = pt*128 + rg + 32*j;
            int r0 = pp - 512 + qp0;
            int r1 = pp - 512 + qp1;
            if (r0 >= 0 && r0 < RR) logits[l0*1024 + r0] += a0[j];
            if (r1 >= 0 && r1 < RR) logits[l1*1024 + r1] += a1[j];
        }
        __syncthreads();
    }

    {
        int lq = tid >> 4, lane = tid & 15;
        int qq = qrow[lq];
        const float* mrow = mask + ((size_t)n*QQ + qq)*RR;
        const int* srow = segmat + ((size_t)n*QQ + qq)*RR;
        float s1v = seg1[lq], s0v = seg0[lq];
        float* lrow = logits + lq*1024;
        float mx = -3.4e38f;
        for (int i = 0; i < 64; i++) {
            int c = lane + 16*i;
            float lg = lrow[c] + (srow[c] ? s1v : s0v);
            lg = lg * 0.125f + mrow[c] * (-1e9f);
            lrow[c] = lg;
            mx = fmaxf(mx, lg);
        }
        for (int o = 8; o; o >>= 1) mx = fmaxf(mx, __shfl_xor_sync(0xffffffffu, mx, o, 16));
        float sum = 0.f;
        for (int i = 0; i < 64; i++) {
            int c = lane + 16*i;
            float e = __expf(lrow[c] - mx);
            lrow[c] = e;
            sum += e;
        }
        for (int o = 8; o; o >>= 1) sum += __shfl_xor_sync(0xffffffffu, sum, o, 16);
        float inv = __fdividef(1.f, sum);
        for (int i = 0; i < 64; i++) lrow[lane + 16*i] *= inv;
    }
    __syncthreads();

    {
        const int sg = rg;
        float b00=0, b01=0, b10=0, b11=0;
        const float* l0row = logits + (qg*2)*1024;
        const float* l1row = l0row + 1024;
        for (int rt = 0; rt < 8; rt++) {
            for (int u = tid; u < 128*16; u += 256) {
                int rl = u >> 4, s4 = u & 15;
                float4 v = *(const float4*)(V + ((((size_t)n*RR + rt*128 + rl)*HH + h) << 6) + s4*4);
                float* d = kt + rl*65 + s4*4;
                d[0]=v.x; d[1]=v.y; d[2]=v.z; d[3]=v.w;
            }
            __syncthreads();
#pragma unroll 4
            for (int rr = 0; rr < 128; rr++) {
                float w0 = l0row[rt*128 + rr];
                float w1 = l1row[rt*128 + rr];
                float v0 = kt[rr*65 + sg];
                float v1 = kt[rr*65 + sg + 32];
                b00 += w0*v0; b01 += w0*v1; b10 += w1*v0; b11 += w1*v1;
            }
            __syncthreads();
        }
        size_t ob = (((size_t)n*NQ + q0 + qg*2)*HH + h)*SS;
        Out[ob + sg]             = b00;
        Out[ob + sg + 32]        = b01;
        Out[ob + 1024 + sg]      = b10;
        Out[ob + 1024 + sg + 32] = b11;
    }
}

// -------------------- launch --------------------
extern "C" void kernel_launch(void* const* d_in, const int* in_sizes, int n_in,
                              void* d_out, int out_size)
{
    const float* content = (const float*)d_in[0];
    const float* query   = (const float*)d_in[1];
    const float* posenc  = (const float*)d_in[2];
    const float* segenc  = (const float*)d_in[3];
    const int*   segmat  = (const int*)d_in[4];
    const float* tmap    = (const float*)d_in[5];
    const float* cmask   = (const float*)d_in[6];
    const float* qmask   = (const float*)d_in[7];
    const float* cb      = (const float*)d_in[8];
    const float* pb      = (const float*)d_in[9];
    const float* sb      = (const float*)d_in[10];
    const float* mems    = (const float*)d_in[11];
    const float* Wq      = (const float*)d_in[12];
    const float* Wkc     = (const float*)d_in[13];
    const float* Wv      = (const float*)d_in[14];
    const float* Wkp     = (const float*)d_in[15];
    const float* Wo      = (const float*)d_in[16];
    float* out = (float*)d_out;

    float *p_ctx, *p_kc, *p_v, *p_kp, *p_qc, *p_qq, *p_ac, *p_aq;
    int* p_tpos;
    cudaGetSymbolAddress((void**)&p_ctx, g_ctx);
    cudaGetSymbolAddress((void**)&p_kc,  g_kc);
    cudaGetSymbolAddress((void**)&p_v,   g_v);
    cudaGetSymbolAddress((void**)&p_kp,  g_kp);
    cudaGetSymbolAddress((void**)&p_qc,  g_qc);
    cudaGetSymbolAddress((void**)&p_qq,  g_qq);
    cudaGetSymbolAddress((void**)&p_ac,  g_ac);
    cudaGetSymbolAddress((void**)&p_aq,  g_aq);
    cudaGetSymbolAddress((void**)&p_tpos, g_tpos);

    cudaFuncSetAttribute(attn_kernel, cudaFuncAttributeMaxDynamicSharedMemorySize, ATTN_SMEM_BYTES);

    build_ctx<<<(BB*RR*HID/4 + 255)/256, 256>>>(mems, content);
    find_tpos<<<1, 512>>>(tmap);

    gemm_mma<<<dim3(8, 32), 256>>>(p_ctx,   Wkc, p_kc);
    gemm_mma<<<dim3(8, 32), 256>>>(p_ctx,   Wv,  p_v);
    gemm_mma<<<dim3(8, 48), 256>>>(posenc,  Wkp, p_kp);
    gemm_mma<<<dim3(8, 16), 256>>>(content, Wq,  p_qc);
    gemm_mma<<<dim3(8, 4),  256>>>(query,   Wq,  p_qq);

    dim3 gac(QQ/16, HH, BB);
    attn_kernel<<<gac, 256, ATTN_SMEM_BYTES>>>(p_qc, QQ, p_kc, p_v, p_kp, segenc, segmat,
                                               cmask, cb, pb, sb, nullptr, p_ac);
    dim3 gaq(PPQ/16, HH, BB);
    attn_kernel<<<gaq, 256, ATTN_SMEM_BYTES>>>(p_qq, PPQ, p_kc, p_v, p_kp, segenc, segmat,
                                               qmask, cb, pb, sb, p_tpos, p_aq);

    gemm_mma<<<dim3(8, 16), 256>>>(p_ac, Wo, out);
    gemm_mma<<<dim3(8, 4),  256>>>(p_aq, Wo, out + (size_t)BB*QQ*HID);
}